// round 10
// baseline (speedup 1.0000x reference)
#include <cuda_runtime.h>
#include <cstdint>

#define BATCH 32
#define HDIM 512
#define WDIM 512
#define NPIX (HDIM * WDIM)
#define KTOP 1000
#define KPRIME (KTOP + 512)
#define NTILES 256
#define MAXTILE 256
#define DELTA 2e-4f

// -------- static device scratch --------
__device__ unsigned long long g_tile[BATCH][NTILES][MAXTILE];
__device__ int g_tcnt[BATCH][NTILES];
__device__ unsigned long long g_lin[BATCH][65536];

// -------- XLA:CPU GenerateVF32Exp (Cephes, non-FMA) — bit-exact reference --------
__device__ __forceinline__ float xla_cpu_expf(float x) {
    const float exp_hi = 88.3762626647950f;
    const float exp_lo = -88.3762626647949f;
    const float log2ef = 1.44269504088896341f;
    const float c1 = 0.693359375f;
    const float c2 = -2.12194440e-4f;

    float xc = fminf(fmaxf(x, exp_lo), exp_hi);
    float fx = floorf(__fadd_rn(__fmul_rn(xc, log2ef), 0.5f));
    float tmp = __fmul_rn(c1, fx);
    float z = __fmul_rn(c2, fx);
    float r = __fsub_rn(xc, tmp);
    r = __fsub_rn(r, z);
    z = __fmul_rn(r, r);

    float y = 1.9875691500E-4f;
    y = __fadd_rn(__fmul_rn(y, r), 1.3981999507E-3f);
    y = __fadd_rn(__fmul_rn(y, r), 8.3334519073E-3f);
    y = __fadd_rn(__fmul_rn(y, r), 4.1665795894E-2f);
    y = __fadd_rn(__fmul_rn(y, r), 1.6666665459E-1f);
    y = __fadd_rn(__fmul_rn(y, r), 5.0000001201E-1f);
    y = __fadd_rn(__fmul_rn(y, z), r);
    y = __fadd_rn(y, 1.0f);

    int emm0 = (((int)fx) + 0x7f) << 23;
    return __fmul_rn(y, __int_as_float(emm0));
}

__device__ __forceinline__ float xla_sigmoidf(float x) {
    float e = xla_cpu_expf(-x);
    return __fdiv_rn(1.0f, __fadd_rn(1.0f, e));
}

__device__ __forceinline__ float score_fn(float r, float u) {
    float s  = xla_sigmoidf(r);
    float p  = __fmul_rn(s, s);
    float su = xla_sigmoidf(u);
    float m  = __fsub_rn(1.0f, __fmul_rn(0.35f, su));
    return __fmul_rn(p, m);
}

// cheap approximate score; |approx - exact| <= ~1e-6 << DELTA
__device__ __forceinline__ float approx_score(float r, float u) {
    float s = __fdividef(1.0f, 1.0f + __expf(-r));
    float m = 1.0f - 0.35f * __fdividef(1.0f, 1.0f + __expf(-u));
    return s * s * m;
}

// -------- kernel 1: approx score + margin NMS -> per-tile candidates --------
__global__ __launch_bounds__(256) void peaks_kernel(const float* __restrict__ route,
                                                    const float* __restrict__ unc) {
    __shared__ float ap[34][35];
    __shared__ unsigned long long sbuf[MAXTILE];
    __shared__ int scnt;

    int b = blockIdx.z;
    int tileId = blockIdx.y * 16 + blockIdx.x;
    int tx0 = blockIdx.x * 32;
    int ty0 = blockIdx.y * 32;
    const float* rp = route + (size_t)b * NPIX;
    const float* up = unc + (size_t)b * NPIX;
    int tid = threadIdx.x;

    if (tid == 0) scnt = 0;

    for (int i = tid; i < 34 * 34; i += 256) {
        int ly = i / 34, lx = i % 34;
        int gx = tx0 - 1 + lx;
        int gy = ty0 - 1 + ly;
        float a = -1e30f;
        if (gx >= 0 && gx < WDIM && gy >= 0 && gy < HDIM) {
            int idx = (gy << 9) | gx;
            a = approx_score(rp[idx], up[idx]);
        }
        ap[ly][lx] = a;
    }
    __syncthreads();

    const int DY[8] = {-1,-1,-1, 0, 0, 1, 1, 1};
    const int DX[8] = {-1, 0, 1,-1, 1,-1, 0, 1};

    for (int rr = 0; rr < 4; rr++) {
        int ly = (tid >> 5) + rr * 8 + 1;
        int lx = (tid & 31) + 1;
        float a = ap[ly][lx];
        bool lose = false;
        bool amb = false;
        #pragma unroll
        for (int j = 0; j < 8; j++) {
            float d = a - ap[ly + DY[j]][lx + DX[j]];
            if (d < -DELTA) lose = true;
            else if (d <= DELTA) amb = true;
        }
        if (!lose) {
            unsigned idx = (unsigned)(((ty0 + ly - 1) << 9) | (tx0 + lx - 1));
            unsigned lo = idx | (amb ? 0x80000000u : 0u);
            unsigned long long key =
                ((unsigned long long)__float_as_uint(a) << 32) | (unsigned long long)lo;
            int p = atomicAdd(&scnt, 1);
            if (p < MAXTILE) sbuf[p] = key;
        }
    }
    __syncthreads();

    int nc = scnt; if (nc > MAXTILE) nc = MAXTILE;
    if (tid == 0) g_tcnt[b][tileId] = nc;
    for (int i = tid; i < nc; i += 256) g_tile[b][tileId][i] = sbuf[i];
}

// -------- bitonic sort (ascending) on 2048-element smem array, 1024 threads --------
__device__ __forceinline__ void bitonic2048(unsigned long long* a, int tid) {
    for (int size = 2; size <= 2048; size <<= 1) {
        for (int stride = size >> 1; stride > 0; stride >>= 1) {
            __syncthreads();
            #pragma unroll
            for (int h = 0; h < 2; h++) {
                int i = tid + h * 1024;
                int j = i ^ stride;
                if (j > i) {
                    bool up = ((i & size) == 0);
                    unsigned long long x = a[i];
                    unsigned long long y = a[j];
                    if ((x > y) == up) { a[i] = y; a[j] = x; }
                }
            }
        }
    }
    __syncthreads();
}

// warp-wide inclusive suffix sum (lane l gets sum over lanes >= l)
__device__ __forceinline__ unsigned warp_suffix(unsigned x, int lane) {
    #pragma unroll
    for (int off = 1; off < 32; off <<= 1) {
        unsigned v = __shfl_down_sync(0xFFFFFFFFu, x, off);
        if (lane + off < 32) x += v;
    }
    return x;
}

// -------- kernel 2: gather + approx top-K' + exact rescore + sort + emit --------
__global__ __launch_bounds__(1024) void select_emit_kernel(const float* __restrict__ route,
                                                           const float* __restrict__ unc,
                                                           const float* __restrict__ scale,
                                                           const int* __restrict__ p_ih,
                                                           const int* __restrict__ p_iw,
                                                           float* __restrict__ out) {
    __shared__ unsigned int hist[4096];
    __shared__ unsigned int P[NTILES + 1];
    __shared__ unsigned int wtot[32];
    __shared__ unsigned int wsuf[33];
    __shared__ unsigned long long skeys[2048];
    __shared__ int sB1, sB2;
    __shared__ unsigned sGt1;
    __shared__ int n_sel;
    __shared__ int n_valid;

    int b = blockIdx.x;
    int tid = threadIdx.x;
    int wid = tid >> 5, lane = tid & 31;

    // ---- phase A: prefix over tile counts (shuffle scan), compact into g_lin ----
    {
        // 256 tiles handled by warps 0..7, ascending prefix via shfl_up
        unsigned c = 0;
        if (tid < NTILES) c = (unsigned)g_tcnt[b][tid];
        unsigned x = c;
        #pragma unroll
        for (int off = 1; off < 32; off <<= 1) {
            unsigned v = __shfl_up_sync(0xFFFFFFFFu, x, off);
            if (lane >= off) x += v;
        }
        if (tid < NTILES && lane == 31) wtot[wid] = x;     // totals of warps 0..7
        __syncthreads();
        if (wid == 0) {
            unsigned w = (lane < 8) ? wtot[lane] : 0u;
            unsigned y = w;
            #pragma unroll
            for (int off = 1; off < 32; off <<= 1) {
                unsigned v = __shfl_up_sync(0xFFFFFFFFu, y, off);
                if (lane >= off) y += v;
            }
            if (lane < 8) wsuf[lane] = y - w;              // exclusive prefix of warp totals
        }
        __syncthreads();
        if (tid < NTILES) P[tid + 1] = x + wsuf[wid];      // inclusive prefix
        if (tid == 0) P[0] = 0;
        __syncthreads();
    }
    int cnt = (int)P[NTILES];

    for (int t = wid; t < NTILES; t += 32) {
        int n = g_tcnt[b][t];
        unsigned base = P[t];
        for (int i = lane; i < n; i += 32)
            g_lin[b][base + i] = g_tile[b][t][i];
    }
    __syncthreads();

    bool need_sel = (cnt > KPRIME);

    if (need_sel) {
        // ---- level 1: warp-aggregated histogram over approx bits [31:20] ----
        #pragma unroll
        for (int j = 0; j < 4; j++) hist[tid * 4 + j] = 0u;
        __syncthreads();
        for (int i = tid; i < cnt; i += 1024) {
            unsigned bin = (unsigned)(g_lin[b][i] >> 52);   // bits [31:20] of score word
            unsigned m = __match_any_sync(__activemask(), bin);
            if (lane == (__ffs(m) - 1)) atomicAdd(&hist[bin], __popc(m));
        }
        __syncthreads();

        // suffix sums via shuffles
        unsigned tsum = hist[tid * 4] + hist[tid * 4 + 1] + hist[tid * 4 + 2] + hist[tid * 4 + 3];
        unsigned x = warp_suffix(tsum, lane);              // sum over lanes >= lane in warp
        if (lane == 0) wtot[wid] = x;
        __syncthreads();
        if (wid == 0) {
            unsigned w = wtot[lane];
            unsigned y = warp_suffix(w, lane);             // sum over warps >= lane
            wsuf[lane] = y;
        }
        __syncthreads();
        {
            unsigned later = (wid + 1 < 32) ? wsuf[wid + 1] : 0u;
            unsigned inc = x + later;                      // sum over tids >= tid
            unsigned above = inc - tsum;                   // sum over tids > tid
            if (above < (unsigned)KPRIME && inc >= (unsigned)KPRIME) {
                unsigned acc = above;
                for (int j = 3; j >= 0; --j) {
                    unsigned c = hist[tid * 4 + j];
                    if (acc + c >= (unsigned)KPRIME) { sB1 = tid * 4 + j; sGt1 = acc; break; }
                    acc += c;
                }
            }
        }
        __syncthreads();

        // ---- level 2: bits [19:8] within boundary bin B1 (warp-aggregated) ----
        int B1 = sB1;
        int k2 = KPRIME - (int)sGt1;
        #pragma unroll
        for (int j = 0; j < 4; j++) hist[tid * 4 + j] = 0u;
        __syncthreads();
        for (int i = tid; i < cnt; i += 1024) {
            unsigned sb = (unsigned)(g_lin[b][i] >> 32);
            if ((int)(sb >> 20) == B1) {
                unsigned bin = (sb >> 8) & 0xFFFu;
                unsigned m = __match_any_sync(__activemask(), bin);
                if (lane == (__ffs(m) - 1)) atomicAdd(&hist[bin], __popc(m));
            }
        }
        __syncthreads();

        tsum = hist[tid * 4] + hist[tid * 4 + 1] + hist[tid * 4 + 2] + hist[tid * 4 + 3];
        x = warp_suffix(tsum, lane);
        if (lane == 0) wtot[wid] = x;
        __syncthreads();
        if (wid == 0) {
            unsigned w = wtot[lane];
            unsigned y = warp_suffix(w, lane);
            wsuf[lane] = y;
        }
        __syncthreads();
        {
            unsigned later = (wid + 1 < 32) ? wsuf[wid + 1] : 0u;
            unsigned inc = x + later;
            unsigned above = inc - tsum;
            if (above < (unsigned)k2 && inc >= (unsigned)k2) {
                unsigned acc = above;
                for (int j = 3; j >= 0; --j) {
                    unsigned c = hist[tid * 4 + j];
                    if (acc + c >= (unsigned)k2) { sB2 = tid * 4 + j; break; }
                    acc += c;
                }
            }
        }
        __syncthreads();
    }

    // ---- phase C: compact selected (approx >= refined boundary), ballot-aggregated ----
    if (tid == 0) { n_sel = 0; n_valid = 0; }
    skeys[tid] = 0ull;
    skeys[tid + 1024] = 0ull;
    __syncthreads();

    if (need_sel) {
        int B1 = sB1, B2 = sB2;
        int end = (cnt + 1023) & ~1023;
        for (int i = tid; i < end; i += 1024) {
            bool valid = (i < cnt);
            unsigned long long key = valid ? g_lin[b][i] : 0ull;
            bool take = false;
            if (valid) {
                unsigned sb = (unsigned)(key >> 32);
                int t12 = (int)(sb >> 20);
                take = (t12 > B1) || (t12 == B1 && (int)((sb >> 8) & 0xFFFu) >= B2);
            }
            unsigned m = __ballot_sync(0xFFFFFFFFu, take);
            if (take) {
                int leader = __ffs(m) - 1;
                int rank = __popc(m & ((1u << lane) - 1u));
                int base = 0;
                if (lane == leader) base = atomicAdd(&n_sel, __popc(m));
                base = __shfl_sync(m, base, leader);
                int p = base + rank;
                if (p < 2048) skeys[p] = key;
            }
        }
    } else {
        for (int i = tid; i < cnt; i += 1024) skeys[i] = g_lin[b][i];  // cnt <= KPRIME
    }
    __syncthreads();

    // ---- phase D: exact rescore of selected; resolve ambiguous peaks exactly ----
    const float* rp = route + (size_t)b * NPIX;
    const float* up = unc + (size_t)b * NPIX;
    const int DY[8] = {-1,-1,-1, 0, 0, 1, 1, 1};
    const int DX[8] = {-1, 0, 1,-1, 1,-1, 0, 1};

    #pragma unroll
    for (int h = 0; h < 2; h++) {
        int i = tid + h * 1024;
        unsigned long long key = skeys[i];
        unsigned long long nk = 0ull;
        bool ok = false;
        if (key != 0ull) {
            unsigned lo = (unsigned)key;
            unsigned idx = lo & 0x3FFFFu;
            bool amb = (lo >> 31) != 0u;
            float v = score_fn(rp[idx], up[idx]);
            ok = true;
            if (amb) {
                int y = (int)(idx >> 9), x = (int)(idx & 511);
                #pragma unroll
                for (int j = 0; j < 8; j++) {
                    int nx = x + DX[j], ny = y + DY[j];
                    if (nx >= 0 && nx < WDIM && ny >= 0 && ny < HDIM) {
                        int nidx = (ny << 9) | nx;
                        float vn = score_fn(rp[nidx], up[nidx]);
                        if (!(v >= vn)) { ok = false; break; }
                    }
                }
            }
            if (ok) {
                nk = ((unsigned long long)__float_as_uint(v) << 32) |
                     (unsigned long long)(~idx);
            }
        }
        skeys[i] = nk;
        unsigned m = __ballot_sync(0xFFFFFFFFu, ok);
        if (lane == 0 && m) atomicAdd(&n_valid, __popc(m));
    }
    __syncthreads();

    // ---- phase E: exact sort, take top KTOP ----
    bitonic2048(skeys, tid);

    int k = n_valid; if (k > KTOP) k = KTOP;

    // ---- phase F: emit ----
    if (tid < KTOP) {
        float iw = (float)p_iw[0];
        float ih = (float)p_ih[0];
        float bcol = 0.f, x1 = 0.f, y1 = 0.f, x2 = 0.f, y2 = 0.f, scv = 0.f, vv = 0.f;
        if (tid < k) {
            unsigned long long key = skeys[2047 - tid];
            float v = __uint_as_float((unsigned)(key >> 32));
            unsigned idx = (~((unsigned)key)) & 0x3FFFFu;
            int y = (int)(idx >> 9);
            int x = (int)(idx & 511);
            float cx = __fmul_rn(__fadd_rn((float)x, 0.5f), 4.0f);
            float cy = __fmul_rn(__fadd_rn((float)y, 0.5f), 4.0f);
            float sc = scale[(size_t)b * NPIX + idx];
            float un = xla_sigmoidf(up[idx]);
            float side = __fadd_rn(32.0f, __fmul_rn(xla_sigmoidf(sc), 480.0f));
            side = __fmul_rn(side, __fadd_rn(1.0f, __fmul_rn(0.25f, un)));
            float half = __fmul_rn(side, 0.5f);
            x1 = fminf(fmaxf(__fsub_rn(cx, half), 0.0f), __fsub_rn(iw, 1.0f));
            y1 = fminf(fmaxf(__fsub_rn(cy, half), 0.0f), __fsub_rn(ih, 1.0f));
            x2 = fminf(fmaxf(__fadd_rn(cx, half), 1.0f), iw);
            y2 = fminf(fmaxf(__fadd_rn(cy, half), 1.0f), ih);
            bcol = (float)b;
            scv = v;
            vv = 1.0f;
        }
        int t = b * KTOP + tid;
        float* roi = out + (size_t)t * 5;
        roi[0] = bcol; roi[1] = x1; roi[2] = y1; roi[3] = x2; roi[4] = y2;
        out[(size_t)BATCH * KTOP * 5 + t] = scv;
        out[(size_t)BATCH * KTOP * 6 + t] = vv;
    }
}

extern "C" void kernel_launch(void* const* d_in, const int* in_sizes, int n_in,
                              void* d_out, int out_size) {
    const float* route = (const float*)d_in[0];
    const float* scale = (const float*)d_in[1];
    const float* uncl  = (const float*)d_in[2];
    const int*   p_ih  = (const int*)d_in[3];
    const int*   p_iw  = (const int*)d_in[4];
    float* out = (float*)d_out;

    dim3 grid(WDIM / 32, HDIM / 32, BATCH);
    peaks_kernel<<<grid, 256>>>(route, uncl);

    select_emit_kernel<<<BATCH, 1024>>>(route, uncl, scale, p_ih, p_iw, out);
}

// round 12
// speedup vs baseline: 1.1005x; 1.1005x over previous
#include <cuda_runtime.h>
#include <cstdint>

#define BATCH 32
#define HDIM 512
#define WDIM 512
#define NPIX (HDIM * WDIM)
#define KTOP 1000
#define KPRIME 1280
#define NTILES 256
#define MAXTILE 256
#define NSEL 2048
#define DELTA 2e-4f

// -------- static device scratch (zero-initialized at module load) --------
__device__ unsigned long long g_tile[BATCH][NTILES][MAXTILE];
__device__ int g_tcnt[BATCH][NTILES];
__device__ unsigned int g_hist[BATCH][4096];   // re-zeroed by select_emit each run

// -------- XLA:CPU GenerateVF32Exp (Cephes, non-FMA) — bit-exact reference --------
__device__ __forceinline__ float xla_cpu_expf(float x) {
    const float exp_hi = 88.3762626647950f;
    const float exp_lo = -88.3762626647949f;
    const float log2ef = 1.44269504088896341f;
    const float c1 = 0.693359375f;
    const float c2 = -2.12194440e-4f;

    float xc = fminf(fmaxf(x, exp_lo), exp_hi);
    float fx = floorf(__fadd_rn(__fmul_rn(xc, log2ef), 0.5f));
    float tmp = __fmul_rn(c1, fx);
    float z = __fmul_rn(c2, fx);
    float r = __fsub_rn(xc, tmp);
    r = __fsub_rn(r, z);
    z = __fmul_rn(r, r);

    float y = 1.9875691500E-4f;
    y = __fadd_rn(__fmul_rn(y, r), 1.3981999507E-3f);
    y = __fadd_rn(__fmul_rn(y, r), 8.3334519073E-3f);
    y = __fadd_rn(__fmul_rn(y, r), 4.1665795894E-2f);
    y = __fadd_rn(__fmul_rn(y, r), 1.6666665459E-1f);
    y = __fadd_rn(__fmul_rn(y, r), 5.0000001201E-1f);
    y = __fadd_rn(__fmul_rn(y, z), r);
    y = __fadd_rn(y, 1.0f);

    int emm0 = (((int)fx) + 0x7f) << 23;
    return __fmul_rn(y, __int_as_float(emm0));
}

__device__ __forceinline__ float xla_sigmoidf(float x) {
    float e = xla_cpu_expf(-x);
    return __fdiv_rn(1.0f, __fadd_rn(1.0f, e));
}

__device__ __forceinline__ float score_fn(float r, float u) {
    float s  = xla_sigmoidf(r);
    float p  = __fmul_rn(s, s);
    float su = xla_sigmoidf(u);
    float m  = __fsub_rn(1.0f, __fmul_rn(0.35f, su));
    return __fmul_rn(p, m);
}

// cheap approximate score; |approx - exact| <= ~1e-5 << DELTA
__device__ __forceinline__ float approx_score(float r, float u) {
    float s = __fdividef(1.0f, 1.0f + __expf(-r));
    float m = 1.0f - 0.35f * __fdividef(1.0f, 1.0f + __expf(-u));
    return s * s * m;
}

// 12-bit monotone bin over score bits: exponent[3:0] + mantissa[22:15].
// Scores live in (0,1); bits [30:27] are constant 0b0111 for exp in [112,127],
// so bits [26:15] are monotone there. Sub-2^-15 scores clamp to bin 0.
__device__ __forceinline__ unsigned binkey_of(unsigned sb) {
    return (sb < 0x38000000u) ? 0u : ((sb >> 15) & 0xFFFu);
}

// warp-wide inclusive suffix sum (lane l gets sum over lanes >= l)
__device__ __forceinline__ unsigned warp_suffix(unsigned x, int lane) {
    #pragma unroll
    for (int off = 1; off < 32; off <<= 1) {
        unsigned v = __shfl_down_sync(0xFFFFFFFFu, x, off);
        if (lane + off < 32) x += v;
    }
    return x;
}

__device__ __forceinline__ unsigned long long ullmin2(unsigned long long a, unsigned long long b) {
    return a < b ? a : b;
}
__device__ __forceinline__ unsigned long long ullmax2(unsigned long long a, unsigned long long b) {
    return a > b ? a : b;
}

// -------- kernel 1: approx score + margin NMS -> per-tile candidates + batch histogram --------
__global__ __launch_bounds__(256) void peaks_kernel(const float* __restrict__ route,
                                                    const float* __restrict__ unc) {
    __shared__ float ap[34][35];
    __shared__ unsigned int sh_hist[4096];
    __shared__ unsigned long long sbuf[MAXTILE];
    __shared__ int scnt;

    int b = blockIdx.z;
    int tileId = blockIdx.y * 16 + blockIdx.x;
    int tx0 = blockIdx.x * 32;
    int ty0 = blockIdx.y * 32;
    const float* rp = route + (size_t)b * NPIX;
    const float* up = unc + (size_t)b * NPIX;
    int tid = threadIdx.x;

    if (tid == 0) scnt = 0;
    for (int i = tid; i < 4096; i += 256) sh_hist[i] = 0u;

    for (int i = tid; i < 34 * 34; i += 256) {
        int ly = i / 34, lx = i % 34;
        int gx = tx0 - 1 + lx;
        int gy = ty0 - 1 + ly;
        float a = -1e30f;
        if (gx >= 0 && gx < WDIM && gy >= 0 && gy < HDIM) {
            int idx = (gy << 9) | gx;
            a = approx_score(rp[idx], up[idx]);
        }
        ap[ly][lx] = a;
    }
    __syncthreads();

    const int DY[8] = {-1,-1,-1, 0, 0, 1, 1, 1};
    const int DX[8] = {-1, 0, 1,-1, 1,-1, 0, 1};

    for (int rr = 0; rr < 4; rr++) {
        int ly = (tid >> 5) + rr * 8 + 1;
        int lx = (tid & 31) + 1;
        float a = ap[ly][lx];
        bool lose = false;
        bool amb = false;
        #pragma unroll
        for (int j = 0; j < 8; j++) {
            float d = a - ap[ly + DY[j]][lx + DX[j]];
            if (d < -DELTA) lose = true;
            else if (d <= DELTA) amb = true;
        }
        if (!lose) {
            unsigned idx = (unsigned)(((ty0 + ly - 1) << 9) | (tx0 + lx - 1));
            unsigned lo = idx | (amb ? 0x80000000u : 0u);
            unsigned sb = __float_as_uint(a);
            unsigned long long key =
                ((unsigned long long)sb << 32) | (unsigned long long)lo;
            int p = atomicAdd(&scnt, 1);
            if (p < MAXTILE) {
                sbuf[p] = key;
                atomicAdd(&sh_hist[binkey_of(sb)], 1u);  // count only stored keys
            }
        }
    }
    __syncthreads();

    int nc = scnt; if (nc > MAXTILE) nc = MAXTILE;
    if (tid == 0) g_tcnt[b][tileId] = nc;
    for (int i = tid; i < nc; i += 256) g_tile[b][tileId][i] = sbuf[i];
    // merge nonzero bins into the per-batch global histogram
    for (int i = tid; i < 4096; i += 256) {
        unsigned c = sh_hist[i];
        if (c) atomicAdd(&g_hist[b][i], c);
    }
}

// -------- kernel 2: threshold from histogram + compact + exact rescore + sort + emit --------
__global__ __launch_bounds__(1024) void select_emit_kernel(const float* __restrict__ route,
                                                           const float* __restrict__ unc,
                                                           const float* __restrict__ scale,
                                                           const int* __restrict__ p_ih,
                                                           const int* __restrict__ p_iw,
                                                           float* __restrict__ out) {
    __shared__ unsigned int hist[4096];
    __shared__ unsigned int wtot[32];
    __shared__ unsigned int wsuf[33];
    __shared__ unsigned long long skeys[NSEL];
    __shared__ int sB;
    __shared__ int n_sel;
    __shared__ int n_valid;

    int b = blockIdx.x;
    int tid = threadIdx.x;
    int wid = tid >> 5, lane = tid & 31;

    if (tid == 0) { sB = 0; n_sel = 0; n_valid = 0; }
    // load per-batch histogram and re-zero it for the next run (deterministic)
    #pragma unroll
    for (int j = 0; j < 4; j++) {
        int i = tid * 4 + j;
        hist[i] = g_hist[b][i];
        g_hist[b][i] = 0u;
    }
    __syncthreads();

    // suffix sums over 4096 bins (thread tid owns bins [4tid, 4tid+4))
    unsigned tsum = hist[tid * 4] + hist[tid * 4 + 1] + hist[tid * 4 + 2] + hist[tid * 4 + 3];
    unsigned x = warp_suffix(tsum, lane);
    if (lane == 0) wtot[wid] = x;
    __syncthreads();
    if (wid == 0) {
        unsigned w = wtot[lane];
        unsigned y = warp_suffix(w, lane);
        wsuf[lane] = y;
    }
    __syncthreads();
    {
        unsigned later = (wid + 1 < 32) ? wsuf[wid + 1] : 0u;
        unsigned inc = x + later;                    // count over bins >= 4tid
        unsigned above = inc - tsum;                 // count over bins >= 4tid+4
        // find max bin with suffix-count >= KPRIME
        if (above < (unsigned)KPRIME && inc >= (unsigned)KPRIME) {
            unsigned acc = above;
            for (int j = 3; j >= 0; --j) {
                unsigned c = hist[tid * 4 + j];
                if (acc + c >= (unsigned)KPRIME) { sB = tid * 4 + j; break; }
                acc += c;
            }
        }
    }
    skeys[tid] = 0ull;
    skeys[tid + 1024] = 0ull;
    __syncthreads();

    // ---- compact pass directly over g_tile: take keys with bin >= B ----
    {
        int B = sB;
        for (int t = wid; t < NTILES; t += 32) {
            int n = g_tcnt[b][t];
            int nr = (n + 31) & ~31;
            for (int i = lane; i < nr; i += 32) {
                bool valid = (i < n);
                unsigned long long key = valid ? g_tile[b][t][i] : 0ull;
                bool take = valid &&
                            (binkey_of((unsigned)(key >> 32)) >= (unsigned)B);
                unsigned m = __ballot_sync(0xFFFFFFFFu, take);
                if (take) {
                    int leader = __ffs(m) - 1;
                    int rank = __popc(m & ((1u << lane) - 1u));
                    int base = 0;
                    if (lane == leader) base = atomicAdd(&n_sel, __popc(m));
                    base = __shfl_sync(m, base, leader);
                    int p = base + rank;
                    if (p < NSEL) skeys[p] = key;
                }
            }
        }
    }
    __syncthreads();

    // ---- exact rescore of selected; resolve ambiguous peaks exactly ----
    const float* rp = route + (size_t)b * NPIX;
    const float* up = unc + (size_t)b * NPIX;
    const int DY[8] = {-1,-1,-1, 0, 0, 1, 1, 1};
    const int DX[8] = {-1, 0, 1,-1, 1,-1, 0, 1};

    #pragma unroll
    for (int h = 0; h < 2; h++) {
        int i = tid + h * 1024;
        unsigned long long key = skeys[i];
        unsigned long long nk = 0ull;
        bool ok = false;
        if (key != 0ull) {
            unsigned lo = (unsigned)key;
            unsigned idx = lo & 0x3FFFFu;
            bool amb = (lo >> 31) != 0u;
            float v = score_fn(rp[idx], up[idx]);
            ok = true;
            if (amb) {
                int y = (int)(idx >> 9), x2i = (int)(idx & 511);
                #pragma unroll
                for (int j = 0; j < 8; j++) {
                    int nx = x2i + DX[j], ny = y + DY[j];
                    if (nx >= 0 && nx < WDIM && ny >= 0 && ny < HDIM) {
                        int nidx = (ny << 9) | nx;
                        float vn = score_fn(rp[nidx], up[nidx]);
                        if (!(v >= vn)) { ok = false; break; }
                    }
                }
            }
            if (ok) {
                nk = ((unsigned long long)__float_as_uint(v) << 32) |
                     (unsigned long long)(~idx);
            }
        }
        skeys[i] = nk;
        unsigned m = __ballot_sync(0xFFFFFFFFu, ok);
        if (lane == 0 && m) atomicAdd(&n_valid, __popc(m));
    }
    __syncthreads();

    // ---- register/shfl bitonic sort of 2048 (ascending; zeros sort to front) ----
    {
        unsigned long long v0 = skeys[tid];
        unsigned long long v1 = skeys[tid + 1024];
        const int i0 = tid, i1 = tid + 1024;

        for (int size = 2; size <= 2048; size <<= 1) {
            for (int stride = size >> 1; stride > 0; stride >>= 1) {
                if (stride == 1024) {
                    // partner is this thread's other element (i1 = i0 ^ 1024)
                    bool up0 = ((i0 & size) == 0);
                    if ((v0 > v1) == up0) { unsigned long long t = v0; v0 = v1; v1 = t; }
                } else if (stride >= 32) {
                    __syncthreads();
                    skeys[i0] = v0; skeys[i1] = v1;
                    __syncthreads();
                    unsigned long long p0 = skeys[i0 ^ stride];
                    unsigned long long p1 = skeys[i1 ^ stride];
                    bool up0 = ((i0 & size) == 0), le0 = ((i0 & stride) == 0);
                    bool up1 = ((i1 & size) == 0), le1 = ((i1 & stride) == 0);
                    v0 = (le0 == up0) ? ullmin2(v0, p0) : ullmax2(v0, p0);
                    v1 = (le1 == up1) ? ullmin2(v1, p1) : ullmax2(v1, p1);
                } else {
                    unsigned long long p0 = __shfl_xor_sync(0xFFFFFFFFu, v0, stride);
                    unsigned long long p1 = __shfl_xor_sync(0xFFFFFFFFu, v1, stride);
                    bool up0 = ((i0 & size) == 0), le0 = ((i0 & stride) == 0);
                    bool up1 = ((i1 & size) == 0), le1 = ((i1 & stride) == 0);
                    v0 = (le0 == up0) ? ullmin2(v0, p0) : ullmax2(v0, p0);
                    v1 = (le1 == up1) ? ullmin2(v1, p1) : ullmax2(v1, p1);
                }
            }
        }
        __syncthreads();
        skeys[i0] = v0; skeys[i1] = v1;
        __syncthreads();
    }

    int k = n_valid; if (k > KTOP) k = KTOP;

    // ---- emit ----
    if (tid < KTOP) {
        float iw = (float)p_iw[0];
        float ih = (float)p_ih[0];
        float bcol = 0.f, x1 = 0.f, y1 = 0.f, x2 = 0.f, y2 = 0.f, scv = 0.f, vv = 0.f;
        if (tid < k) {
            unsigned long long key = skeys[2047 - tid];
            float v = __uint_as_float((unsigned)(key >> 32));
            unsigned idx = (~((unsigned)key)) & 0x3FFFFu;
            int y = (int)(idx >> 9);
            int x = (int)(idx & 511);
            float cx = __fmul_rn(__fadd_rn((float)x, 0.5f), 4.0f);
            float cy = __fmul_rn(__fadd_rn((float)y, 0.5f), 4.0f);
            float sc = scale[(size_t)b * NPIX + idx];
            float un = xla_sigmoidf(up[idx]);
            float side = __fadd_rn(32.0f, __fmul_rn(xla_sigmoidf(sc), 480.0f));
            side = __fmul_rn(side, __fadd_rn(1.0f, __fmul_rn(0.25f, un)));
            float half = __fmul_rn(side, 0.5f);
            x1 = fminf(fmaxf(__fsub_rn(cx, half), 0.0f), __fsub_rn(iw, 1.0f));
            y1 = fminf(fmaxf(__fsub_rn(cy, half), 0.0f), __fsub_rn(ih, 1.0f));
            x2 = fminf(fmaxf(__fadd_rn(cx, half), 1.0f), iw);
            y2 = fminf(fmaxf(__fadd_rn(cy, half), 1.0f), ih);
            bcol = (float)b;
            scv = v;
            vv = 1.0f;
        }
        int t = b * KTOP + tid;
        float* roi = out + (size_t)t * 5;
        roi[0] = bcol; roi[1] = x1; roi[2] = y1; roi[3] = x2; roi[4] = y2;
        out[(size_t)BATCH * KTOP * 5 + t] = scv;
        out[(size_t)BATCH * KTOP * 6 + t] = vv;
    }
}

extern "C" void kernel_launch(void* const* d_in, const int* in_sizes, int n_in,
                              void* d_out, int out_size) {
    const float* route = (const float*)d_in[0];
    const float* scale = (const float*)d_in[1];
    const float* uncl  = (const float*)d_in[2];
    const int*   p_ih  = (const int*)d_in[3];
    const int*   p_iw  = (const int*)d_in[4];
    float* out = (float*)d_out;

    dim3 grid(WDIM / 32, HDIM / 32, BATCH);
    peaks_kernel<<<grid, 256>>>(route, uncl);

    select_emit_kernel<<<BATCH, 1024>>>(route, uncl, scale, p_ih, p_iw, out);
}

// round 13
// speedup vs baseline: 1.3195x; 1.1991x over previous
#include <cuda_runtime.h>
#include <cstdint>

#define BATCH 32
#define HDIM 512
#define WDIM 512
#define NPIX (HDIM * WDIM)
#define KTOP 1000
#define KPRIME 1280
#define NTILES 256
#define MAXTILE 256
#define TPC 16            // tiles per prepare-CTA
#define NSEL 2048
#define STAGE_CAP 1536
#define HBINS 2048
#define DELTA 2e-4f

// -------- static device scratch (zero-initialized at module load) --------
__device__ unsigned long long g_tile[BATCH][NTILES][MAXTILE];
__device__ int g_tcnt[BATCH][NTILES];
__device__ unsigned int g_hist[BATCH][HBINS];        // re-zeroed by sort_emit
__device__ unsigned long long g_sel[BATCH][NSEL];
__device__ int g_nsel[BATCH];                        // re-zeroed by sort_emit

// -------- XLA:CPU GenerateVF32Exp (Cephes, non-FMA) — bit-exact reference --------
__device__ __forceinline__ float xla_cpu_expf(float x) {
    const float exp_hi = 88.3762626647950f;
    const float exp_lo = -88.3762626647949f;
    const float log2ef = 1.44269504088896341f;
    const float c1 = 0.693359375f;
    const float c2 = -2.12194440e-4f;

    float xc = fminf(fmaxf(x, exp_lo), exp_hi);
    float fx = floorf(__fadd_rn(__fmul_rn(xc, log2ef), 0.5f));
    float tmp = __fmul_rn(c1, fx);
    float z = __fmul_rn(c2, fx);
    float r = __fsub_rn(xc, tmp);
    r = __fsub_rn(r, z);
    z = __fmul_rn(r, r);

    float y = 1.9875691500E-4f;
    y = __fadd_rn(__fmul_rn(y, r), 1.3981999507E-3f);
    y = __fadd_rn(__fmul_rn(y, r), 8.3334519073E-3f);
    y = __fadd_rn(__fmul_rn(y, r), 4.1665795894E-2f);
    y = __fadd_rn(__fmul_rn(y, r), 1.6666665459E-1f);
    y = __fadd_rn(__fmul_rn(y, r), 5.0000001201E-1f);
    y = __fadd_rn(__fmul_rn(y, z), r);
    y = __fadd_rn(y, 1.0f);

    int emm0 = (((int)fx) + 0x7f) << 23;
    return __fmul_rn(y, __int_as_float(emm0));
}

__device__ __forceinline__ float xla_sigmoidf(float x) {
    float e = xla_cpu_expf(-x);
    return __fdiv_rn(1.0f, __fadd_rn(1.0f, e));
}

__device__ __forceinline__ float score_fn(float r, float u) {
    float s  = xla_sigmoidf(r);
    float p  = __fmul_rn(s, s);
    float su = xla_sigmoidf(u);
    float m  = __fsub_rn(1.0f, __fmul_rn(0.35f, su));
    return __fmul_rn(p, m);
}

// cheap approximate score; |approx - exact| <= ~1e-5 << DELTA
__device__ __forceinline__ float approx_score(float r, float u) {
    float s = __fdividef(1.0f, 1.0f + __expf(-r));
    float m = 1.0f - 0.35f * __fdividef(1.0f, 1.0f + __expf(-u));
    return s * s * m;
}

// 11-bit-equivalent monotone bin over score bits: exponents 119..126 (scores in
// [2^-8, 1)), 8 mantissa bits. Lower scores clamp to bin 0 (threshold is never
// that low: ~29k candidates, median score ~0.2).
__device__ __forceinline__ unsigned binkey_of(unsigned sb) {
    return (sb < 0x3B800000u) ? 0u : (((sb >> 15) & 0xFFFu) - 1792u);
}

// warp-wide inclusive suffix sum (lane l gets sum over lanes >= l)
__device__ __forceinline__ unsigned warp_suffix(unsigned x, int lane) {
    #pragma unroll
    for (int off = 1; off < 32; off <<= 1) {
        unsigned v = __shfl_down_sync(0xFFFFFFFFu, x, off);
        if (lane + off < 32) x += v;
    }
    return x;
}

__device__ __forceinline__ unsigned long long ullmin2(unsigned long long a, unsigned long long b) {
    return a < b ? a : b;
}
__device__ __forceinline__ unsigned long long ullmax2(unsigned long long a, unsigned long long b) {
    return a > b ? a : b;
}

// -------- kernel 1: approx score + margin NMS -> per-tile candidates + batch histogram --------
__global__ __launch_bounds__(256) void peaks_kernel(const float* __restrict__ route,
                                                    const float* __restrict__ unc) {
    __shared__ float ap[34][35];
    __shared__ unsigned int sh_hist[HBINS];
    __shared__ unsigned long long sbuf[MAXTILE];
    __shared__ int scnt;

    int b = blockIdx.z;
    int tileId = blockIdx.y * 16 + blockIdx.x;
    int tx0 = blockIdx.x * 32;
    int ty0 = blockIdx.y * 32;
    const float* rp = route + (size_t)b * NPIX;
    const float* up = unc + (size_t)b * NPIX;
    int tid = threadIdx.x;

    if (tid == 0) scnt = 0;
    for (int i = tid; i < HBINS; i += 256) sh_hist[i] = 0u;

    for (int i = tid; i < 34 * 34; i += 256) {
        int ly = i / 34, lx = i % 34;
        int gx = tx0 - 1 + lx;
        int gy = ty0 - 1 + ly;
        float a = -1e30f;
        if (gx >= 0 && gx < WDIM && gy >= 0 && gy < HDIM) {
            int idx = (gy << 9) | gx;
            a = approx_score(rp[idx], up[idx]);
        }
        ap[ly][lx] = a;
    }
    __syncthreads();

    const int DY[8] = {-1,-1,-1, 0, 0, 1, 1, 1};
    const int DX[8] = {-1, 0, 1,-1, 1,-1, 0, 1};

    for (int rr = 0; rr < 4; rr++) {
        int ly = (tid >> 5) + rr * 8 + 1;
        int lx = (tid & 31) + 1;
        float a = ap[ly][lx];
        bool lose = false;
        bool amb = false;
        #pragma unroll
        for (int j = 0; j < 8; j++) {
            float d = a - ap[ly + DY[j]][lx + DX[j]];
            if (d < -DELTA) lose = true;
            else if (d <= DELTA) amb = true;
        }
        if (!lose) {
            unsigned idx = (unsigned)(((ty0 + ly - 1) << 9) | (tx0 + lx - 1));
            unsigned lo = idx | (amb ? 0x80000000u : 0u);
            unsigned sb = __float_as_uint(a);
            unsigned long long key =
                ((unsigned long long)sb << 32) | (unsigned long long)lo;
            int p = atomicAdd(&scnt, 1);
            if (p < MAXTILE) {
                sbuf[p] = key;
                atomicAdd(&sh_hist[binkey_of(sb)], 1u);  // count only stored keys
            }
        }
    }
    __syncthreads();

    int nc = scnt; if (nc > MAXTILE) nc = MAXTILE;
    if (tid == 0) g_tcnt[b][tileId] = nc;
    for (int i = tid; i < nc; i += 256) g_tile[b][tileId][i] = sbuf[i];
    for (int i = tid; i < HBINS; i += 256) {
        unsigned c = sh_hist[i];
        if (c) atomicAdd(&g_hist[b][i], c);
    }
}

// -------- kernel 2: per-batch threshold + compact + exact rescore (512 CTAs) --------
__global__ __launch_bounds__(256) void prepare_kernel(const float* __restrict__ route,
                                                      const float* __restrict__ unc) {
    __shared__ unsigned long long sbuf[STAGE_CAP];
    __shared__ unsigned int wtot[8];
    __shared__ unsigned int wsuf[32];
    __shared__ int sB;
    __shared__ int s_stage;

    int b = blockIdx.y;
    int t0 = blockIdx.x * TPC;
    int tid = threadIdx.x;
    int wid = tid >> 5, lane = tid & 31;

    if (tid == 0) { sB = 0; s_stage = 0; }
    __syncthreads();

    // ---- threshold scan: thread owns bins [8*tid, 8*tid+8) of g_hist[b] ----
    unsigned hb[8];
    unsigned tsum = 0;
    #pragma unroll
    for (int j = 0; j < 8; j++) { hb[j] = g_hist[b][tid * 8 + j]; tsum += hb[j]; }
    unsigned x = warp_suffix(tsum, lane);
    if (lane == 0) wtot[wid] = x;
    __syncthreads();
    if (wid == 0) {
        unsigned w = (lane < 8) ? wtot[lane] : 0u;
        unsigned y = warp_suffix(w, lane);
        wsuf[lane] = y;
    }
    __syncthreads();
    {
        unsigned later = (wid + 1 < 8) ? wsuf[wid + 1] : 0u;
        unsigned inc = x + later;                 // count over bins >= 8*tid
        unsigned above = inc - tsum;              // count over bins >= 8*tid+8
        if (above < (unsigned)KPRIME && inc >= (unsigned)KPRIME) {
            unsigned acc = above;
            for (int j = 7; j >= 0; --j) {
                if (acc + hb[j] >= (unsigned)KPRIME) { sB = tid * 8 + j; break; }
                acc += hb[j];
            }
        }
    }
    __syncthreads();
    int B = sB;

    // ---- compact this CTA's TPC tiles: keys with bin >= B -> smem stage ----
    for (int t = t0 + wid; t < t0 + TPC; t += 8) {
        int n = g_tcnt[b][t];
        int nr = (n + 31) & ~31;
        for (int i = lane; i < nr; i += 32) {
            bool valid = (i < n);
            unsigned long long key = valid ? g_tile[b][t][i] : 0ull;
            bool take = valid &&
                        (binkey_of((unsigned)(key >> 32)) >= (unsigned)B);
            unsigned m = __ballot_sync(0xFFFFFFFFu, take);
            if (take) {
                int leader = __ffs(m) - 1;
                int rank = __popc(m & ((1u << lane) - 1u));
                int base = 0;
                if (lane == leader) base = atomicAdd(&s_stage, __popc(m));
                base = __shfl_sync(m, base, leader);
                int p = base + rank;
                if (p < STAGE_CAP) sbuf[p] = key;
            }
        }
    }
    __syncthreads();

    // ---- exact rescore of staged keys; survivors -> g_sel[b] ----
    const float* rp = route + (size_t)b * NPIX;
    const float* up = unc + (size_t)b * NPIX;
    const int DY[8] = {-1,-1,-1, 0, 0, 1, 1, 1};
    const int DX[8] = {-1, 0, 1,-1, 1,-1, 0, 1};

    int m = s_stage; if (m > STAGE_CAP) m = STAGE_CAP;
    int mr = (m + 255) & ~255;
    for (int i = tid; i < mr; i += 256) {
        bool valid = (i < m);
        unsigned long long nk = 0ull;
        bool ok = false;
        if (valid) {
            unsigned lo = (unsigned)sbuf[i];
            unsigned idx = lo & 0x3FFFFu;
            bool amb = (lo >> 31) != 0u;
            float v = score_fn(rp[idx], up[idx]);
            ok = true;
            if (amb) {
                int y = (int)(idx >> 9), x2i = (int)(idx & 511);
                #pragma unroll
                for (int j = 0; j < 8; j++) {
                    int nx = x2i + DX[j], ny = y + DY[j];
                    if (nx >= 0 && nx < WDIM && ny >= 0 && ny < HDIM) {
                        int nidx = (ny << 9) | nx;
                        float vn = score_fn(rp[nidx], up[nidx]);
                        if (!(v >= vn)) { ok = false; break; }
                    }
                }
            }
            if (ok) {
                nk = ((unsigned long long)__float_as_uint(v) << 32) |
                     (unsigned long long)(~idx);
            }
        }
        unsigned bm = __ballot_sync(0xFFFFFFFFu, ok);
        if (ok) {
            int leader = __ffs(bm) - 1;
            int rank = __popc(bm & ((1u << lane) - 1u));
            int base = 0;
            if (lane == leader) base = atomicAdd(&g_nsel[b], __popc(bm));
            base = __shfl_sync(bm, base, leader);
            int p = base + rank;
            if (p < NSEL) g_sel[b][p] = nk;
        }
    }
}

// -------- kernel 3: sort exact keys + emit (32 CTAs) --------
__global__ __launch_bounds__(1024) void sort_emit_kernel(const float* __restrict__ unc,
                                                         const float* __restrict__ scale,
                                                         const int* __restrict__ p_ih,
                                                         const int* __restrict__ p_iw,
                                                         float* __restrict__ out) {
    __shared__ unsigned long long skeys[NSEL];

    int b = blockIdx.x;
    int tid = threadIdx.x;

    int n = g_nsel[b]; if (n > NSEL) n = NSEL;
    skeys[tid]        = (tid < n)        ? g_sel[b][tid]        : 0ull;
    skeys[tid + 1024] = (tid + 1024 < n) ? g_sel[b][tid + 1024] : 0ull;
    __syncthreads();

    // register/shfl bitonic sort of 2048 (ascending; zeros sort to front)
    {
        unsigned long long v0 = skeys[tid];
        unsigned long long v1 = skeys[tid + 1024];
        const int i0 = tid, i1 = tid + 1024;

        for (int size = 2; size <= 2048; size <<= 1) {
            for (int stride = size >> 1; stride > 0; stride >>= 1) {
                if (stride == 1024) {
                    bool up0 = ((i0 & size) == 0);
                    if ((v0 > v1) == up0) { unsigned long long t = v0; v0 = v1; v1 = t; }
                } else if (stride >= 32) {
                    __syncthreads();
                    skeys[i0] = v0; skeys[i1] = v1;
                    __syncthreads();
                    unsigned long long p0 = skeys[i0 ^ stride];
                    unsigned long long p1 = skeys[i1 ^ stride];
                    bool up0 = ((i0 & size) == 0), le0 = ((i0 & stride) == 0);
                    bool up1 = ((i1 & size) == 0), le1 = ((i1 & stride) == 0);
                    v0 = (le0 == up0) ? ullmin2(v0, p0) : ullmax2(v0, p0);
                    v1 = (le1 == up1) ? ullmin2(v1, p1) : ullmax2(v1, p1);
                } else {
                    unsigned long long p0 = __shfl_xor_sync(0xFFFFFFFFu, v0, stride);
                    unsigned long long p1 = __shfl_xor_sync(0xFFFFFFFFu, v1, stride);
                    bool up0 = ((i0 & size) == 0), le0 = ((i0 & stride) == 0);
                    bool up1 = ((i1 & size) == 0), le1 = ((i1 & stride) == 0);
                    v0 = (le0 == up0) ? ullmin2(v0, p0) : ullmax2(v0, p0);
                    v1 = (le1 == up1) ? ullmin2(v1, p1) : ullmax2(v1, p1);
                }
            }
        }
        __syncthreads();
        skeys[i0] = v0; skeys[i1] = v1;
        __syncthreads();
    }

    int k = n; if (k > KTOP) k = KTOP;
    const float* up = unc + (size_t)b * NPIX;

    if (tid < KTOP) {
        float iw = (float)p_iw[0];
        float ih = (float)p_ih[0];
        float bcol = 0.f, x1 = 0.f, y1 = 0.f, x2 = 0.f, y2 = 0.f, scv = 0.f, vv = 0.f;
        if (tid < k) {
            unsigned long long key = skeys[2047 - tid];
            float v = __uint_as_float((unsigned)(key >> 32));
            unsigned idx = (~((unsigned)key)) & 0x3FFFFu;
            int y = (int)(idx >> 9);
            int x = (int)(idx & 511);
            float cx = __fmul_rn(__fadd_rn((float)x, 0.5f), 4.0f);
            float cy = __fmul_rn(__fadd_rn((float)y, 0.5f), 4.0f);
            float sc = scale[(size_t)b * NPIX + idx];
            float un = xla_sigmoidf(up[idx]);
            float side = __fadd_rn(32.0f, __fmul_rn(xla_sigmoidf(sc), 480.0f));
            side = __fmul_rn(side, __fadd_rn(1.0f, __fmul_rn(0.25f, un)));
            float half = __fmul_rn(side, 0.5f);
            x1 = fminf(fmaxf(__fsub_rn(cx, half), 0.0f), __fsub_rn(iw, 1.0f));
            y1 = fminf(fmaxf(__fsub_rn(cy, half), 0.0f), __fsub_rn(ih, 1.0f));
            x2 = fminf(fmaxf(__fadd_rn(cx, half), 1.0f), iw);
            y2 = fminf(fmaxf(__fadd_rn(cy, half), 1.0f), ih);
            bcol = (float)b;
            scv = v;
            vv = 1.0f;
        }
        int t = b * KTOP + tid;
        float* roi = out + (size_t)t * 5;
        roi[0] = bcol; roi[1] = x1; roi[2] = y1; roi[3] = x2; roi[4] = y2;
        out[(size_t)BATCH * KTOP * 5 + t] = scv;
        out[(size_t)BATCH * KTOP * 6 + t] = vv;
    }

    // cleanup for next graph replay (deterministic state)
    for (int i = tid; i < HBINS; i += 1024) g_hist[b][i] = 0u;
    if (tid == 0) g_nsel[b] = 0;
}

extern "C" void kernel_launch(void* const* d_in, const int* in_sizes, int n_in,
                              void* d_out, int out_size) {
    const float* route = (const float*)d_in[0];
    const float* scale = (const float*)d_in[1];
    const float* uncl  = (const float*)d_in[2];
    const int*   p_ih  = (const int*)d_in[3];
    const int*   p_iw  = (const int*)d_in[4];
    float* out = (float*)d_out;

    dim3 grid1(WDIM / 32, HDIM / 32, BATCH);
    peaks_kernel<<<grid1, 256>>>(route, uncl);

    dim3 grid2(NTILES / TPC, BATCH);
    prepare_kernel<<<grid2, 256>>>(route, uncl);

    sort_emit_kernel<<<BATCH, 1024>>>(uncl, scale, p_ih, p_iw, out);
}